// round 5
// baseline (speedup 1.0000x reference)
#include <cuda_runtime.h>
#include <stdint.h>

// Problem constants (fixed shapes per setup_inputs)
#define BATCH 4
#define NPTS  2048
#define NB    (BATCH * NPTS)        // 8192 (b,n) pairs
#define GRID_DIM 64                 // coords in [0,64)
#define BITMAP_WORDS (GRID_DIM * GRID_DIM * GRID_DIM / 32)  // 8192 words / batch
#define PRIOR_VOX 4096              // 16^3
#define OCC_K 26
#define OCC_BASE ((size_t)NB * PRIOR_VOX)   // 33,554,432

// Scratch (static __device__ per harness rules):
__device__ unsigned int  g_bitmap[BATCH * BITMAP_WORDS];  // 128 KB occupancy bits
__device__ unsigned char g_mask[NB];                      // 6-bit face mask per (b,n)

// 26 neighbor offsets; first 6 are the face offsets (order matches reference).
__constant__ int8_t c_noff[26][3] = {
    {-1,0,0},{1,0,0},{0,-1,0},{0,1,0},{0,0,-1},{0,0,1},
    {-1,-1,0},{-1,1,0},{1,-1,0},{1,1,0},
    {-1,0,-1},{-1,0,1},{1,0,-1},{1,0,1},
    {0,-1,-1},{0,-1,1},{0,1,-1},{0,1,1},
    {-1,-1,-1},{-1,-1,1},{-1,1,-1},{-1,1,1},
    {1,-1,-1},{1,-1,1},{1,1,-1},{1,1,1}};

// Fused zero + build + probe. One CTA per batch, 1024 threads.
// Phase 1: zero this batch's bitmap slice. Phase 2: atomicOr the 2048 points.
// Phase 3: each thread probes 26 neighbors for 2 points (via __ldcg to bypass
// possibly-stale L1 lines from the zeroing stores), writes occ + face mask.
__global__ __launch_bounds__(1024)
void build_probe_kernel(const int* __restrict__ coords, float* __restrict__ out) {
    const int b = blockIdx.x;
    const int t = threadIdx.x;
    unsigned int* bm = g_bitmap + b * BITMAP_WORDS;

    #pragma unroll
    for (int i = 0; i < BITMAP_WORDS / 1024; i++)
        bm[t + i * 1024] = 0u;
    __syncthreads();

    const int* c = coords + b * NPTS * 3;
    #pragma unroll
    for (int i = 0; i < NPTS / 1024; i++) {
        int n = t + i * 1024;
        int x = c[n * 3 + 0];
        int y = c[n * 3 + 1];
        int z = c[n * 3 + 2];
        int idx = (x << 12) | (y << 6) | z;    // x*4096 + y*64 + z
        atomicOr(&bm[idx >> 5], 1u << (idx & 31));
    }
    __syncthreads();

    #pragma unroll
    for (int i = 0; i < NPTS / 1024; i++) {
        int n  = t + i * 1024;
        int bn = b * NPTS + n;
        int x = c[n * 3 + 0];
        int y = c[n * 3 + 1];
        int z = c[n * 3 + 2];
        unsigned mask26 = 0;
        #pragma unroll
        for (int k = 0; k < OCC_K; k++) {
            int nx = x + c_noff[k][0];
            int ny = y + c_noff[k][1];
            int nz = z + c_noff[k][2];
            if ((unsigned)nx < GRID_DIM && (unsigned)ny < GRID_DIM &&
                (unsigned)nz < GRID_DIM) {
                int idx = (nx << 12) | (ny << 6) | nz;
                unsigned w = __ldcg(&bm[idx >> 5]);   // L2 read (skip L1)
                mask26 |= ((w >> (idx & 31)) & 1u) << k;
            }
        }
        float* occ_p = out + OCC_BASE + (size_t)bn * OCC_K;
        #pragma unroll
        for (int k = 0; k < OCC_K; k++)
            occ_p[k] = (mask26 >> k) & 1u ? 1.0f : 0.0f;
        g_mask[bn] = (unsigned char)(mask26 & 63u);
    }
}

// Pure store stream. One CTA per (b,n), 256 threads, no smem, no sync.
// Each thread emits 4 float4 at v = t*4 + q*1024 -> each warp store is a
// fully contiguous 512B write.
__global__ __launch_bounds__(256, 8)
void prior_kernel(float* __restrict__ out) {
    const int bn = blockIdx.x;
    const int t  = threadIdx.x;
    const unsigned m = g_mask[bn];          // converged broadcast load

    const float r15 = 1.0f / 15.0f;
    float* out_p = out + (size_t)bn * PRIOR_VOX;

    // Voxel v = i*256 + j*16 + k; dists = [i/15, 1-i/15, j/15, 1-j/15, k/15, 1-k/15]
    // prior[v] = min over faces f of (has_nb[f] ? 1.0 : dist[f])
    #pragma unroll
    for (int q = 0; q < 4; q++) {
        int v  = (t << 2) + (q << 10);
        int i  = v >> 8;
        int j  = (v >> 4) & 15;
        int k0 = v & 15;               // multiple of 4 within a row of 16
        float gx = (float)i * r15;
        float gy = (float)j * r15;
        float base = 1.0f;
        if (!(m & 1u))  base = fminf(base, gx);
        if (!(m & 2u))  base = fminf(base, 1.0f - gx);
        if (!(m & 4u))  base = fminf(base, gy);
        if (!(m & 8u))  base = fminf(base, 1.0f - gy);
        float4 r;
        float* rp = &r.x;
        #pragma unroll
        for (int kk = 0; kk < 4; kk++) {
            float gz = (float)(k0 + kk) * r15;
            float val = base;
            if (!(m & 16u)) val = fminf(val, gz);
            if (!(m & 32u)) val = fminf(val, 1.0f - gz);
            rp[kk] = val;
        }
        *reinterpret_cast<float4*>(out_p + v) = r;
    }
}

extern "C" void kernel_launch(void* const* d_in, const int* in_sizes, int n_in,
                              void* d_out, int out_size) {
    const int* coords = (const int*)d_in[0];
    float* out = (float*)d_out;

    build_probe_kernel<<<BATCH, 1024>>>(coords, out);
    prior_kernel<<<NB, 256>>>(out);
}

// round 6
// speedup vs baseline: 1.5201x; 1.5201x over previous
#include <cuda_runtime.h>
#include <stdint.h>

// Problem constants (fixed shapes per setup_inputs)
#define BATCH 4
#define NPTS  2048
#define NB    (BATCH * NPTS)        // 8192 (b,n) pairs
#define GRID_DIM 64                 // coords in [0,64)
#define BITMAP_WORDS (GRID_DIM * GRID_DIM * GRID_DIM / 32)  // 8192 words / batch
#define PRIOR_VOX 4096              // 16^3
#define OCC_K 26
#define OCC_BASE ((size_t)NB * PRIOR_VOX)   // 33,554,432

// Scratch (static __device__ per harness rules):
__device__ unsigned int g_bitmap[BATCH * BITMAP_WORDS];  // 128 KB occupancy bits
__device__ unsigned int g_mask26[NB];                    // 26-bit neighbor mask per (b,n)

// 26 neighbor offsets; first 6 are the face offsets (order matches reference).
__constant__ int8_t c_noff[26][3] = {
    {-1,0,0},{1,0,0},{0,-1,0},{0,1,0},{0,0,-1},{0,0,1},
    {-1,-1,0},{-1,1,0},{1,-1,0},{1,1,0},
    {-1,0,-1},{-1,0,1},{1,0,-1},{1,0,1},
    {0,-1,-1},{0,-1,1},{0,1,-1},{0,1,1},
    {-1,-1,-1},{-1,-1,1},{-1,1,-1},{-1,1,1},
    {1,-1,-1},{1,-1,1},{1,1,-1},{1,1,1}};

// Fused zero + build + probe. One CTA per batch, 1024 threads.
// Phase 1: zero bitmap slice. Phase 2: atomicOr the 2048 points.
// Phase 3: probe 26 neighbors per point (__ldcg: L2, skip stale L1) and store
// ONLY the packed 26-bit mask (coalesced 4B stores). No scattered occ writes
// here — that was the R5 disaster (sector storm on 4 SMs).
__global__ __launch_bounds__(1024)
void build_probe_kernel(const int* __restrict__ coords) {
    const int b = blockIdx.x;
    const int t = threadIdx.x;
    unsigned int* bm = g_bitmap + b * BITMAP_WORDS;

    #pragma unroll
    for (int i = 0; i < BITMAP_WORDS / 1024; i++)
        bm[t + i * 1024] = 0u;
    __syncthreads();

    const int* c = coords + b * NPTS * 3;
    #pragma unroll
    for (int i = 0; i < NPTS / 1024; i++) {
        int n = t + i * 1024;
        int x = c[n * 3 + 0];
        int y = c[n * 3 + 1];
        int z = c[n * 3 + 2];
        int idx = (x << 12) | (y << 6) | z;    // x*4096 + y*64 + z
        atomicOr(&bm[idx >> 5], 1u << (idx & 31));
    }
    __syncthreads();

    #pragma unroll
    for (int i = 0; i < NPTS / 1024; i++) {
        int n  = t + i * 1024;
        int x = c[n * 3 + 0];
        int y = c[n * 3 + 1];
        int z = c[n * 3 + 2];
        unsigned mask26 = 0;
        #pragma unroll
        for (int k = 0; k < OCC_K; k++) {
            int nx = x + c_noff[k][0];
            int ny = y + c_noff[k][1];
            int nz = z + c_noff[k][2];
            if ((unsigned)nx < GRID_DIM && (unsigned)ny < GRID_DIM &&
                (unsigned)nz < GRID_DIM) {
                int idx = (nx << 12) | (ny << 6) | nz;
                unsigned w = __ldcg(&bm[idx >> 5]);   // L2 read (skip L1)
                mask26 |= ((w >> (idx & 31)) & 1u) << k;
            }
        }
        g_mask26[b * NPTS + n] = mask26;              // coalesced 4B store
    }
}

// One CTA per (b,n), 256 threads, no smem, no sync.
// Threads 0..25 write occ; all 256 threads stream the 4096-float prior tile
// as 4 fully contiguous warp-wide float4 stores each.
__global__ __launch_bounds__(256, 8)
void prior_occ_kernel(float* __restrict__ out) {
    const int bn = blockIdx.x;
    const int t  = threadIdx.x;
    const unsigned m26 = g_mask26[bn];      // converged broadcast load
    const unsigned m   = m26 & 63u;

    if (t < OCC_K)
        out[OCC_BASE + (size_t)bn * OCC_K + t] = (m26 >> t) & 1u ? 1.0f : 0.0f;

    const float r15 = 1.0f / 15.0f;
    float* out_p = out + (size_t)bn * PRIOR_VOX;

    // v = t*4 + q*1024; i = (t>>6) + 4q, j = (t>>2)&15, k0 = (t&3)*4.
    // Per-thread invariants across q: gy (y faces) and the 4 z values.
    const float gy  = (float)((t >> 2) & 15) * r15;
    const int   k0  = (t & 3) << 2;
    const float gx0 = (float)(t >> 6) * r15;

    float ybase = 1.0f;
    if (!(m & 4u))  ybase = fminf(ybase, gy);
    if (!(m & 8u))  ybase = fminf(ybase, 1.0f - gy);

    float yz[4];
    #pragma unroll
    for (int kk = 0; kk < 4; kk++) {
        float gz = (float)(k0 + kk) * r15;
        float v = ybase;
        if (!(m & 16u)) v = fminf(v, gz);
        if (!(m & 32u)) v = fminf(v, 1.0f - gz);
        yz[kk] = v;
    }

    #pragma unroll
    for (int q = 0; q < 4; q++) {
        float gx = gx0 + (float)(4 * q) * r15;
        float xv = 1.0f;
        if (!(m & 1u)) xv = fminf(xv, gx);
        if (!(m & 2u)) xv = fminf(xv, 1.0f - gx);
        float4 r;
        r.x = fminf(yz[0], xv);
        r.y = fminf(yz[1], xv);
        r.z = fminf(yz[2], xv);
        r.w = fminf(yz[3], xv);
        *reinterpret_cast<float4*>(out_p + (t << 2) + (q << 10)) = r;
    }
}

extern "C" void kernel_launch(void* const* d_in, const int* in_sizes, int n_in,
                              void* d_out, int out_size) {
    const int* coords = (const int*)d_in[0];
    float* out = (float*)d_out;

    build_probe_kernel<<<BATCH, 1024>>>(coords);
    prior_occ_kernel<<<NB, 256>>>(out);
}

// round 7
// speedup vs baseline: 2.7339x; 1.7984x over previous
#include <cuda_runtime.h>
#include <stdint.h>

// Problem constants (fixed shapes per setup_inputs)
#define BATCH 4
#define NPTS  2048
#define NB    (BATCH * NPTS)        // 8192 (b,n) pairs
#define GRID_DIM 64                 // coords in [0,64)
#define BITMAP_WORDS (GRID_DIM * GRID_DIM * GRID_DIM / 32)  // 8192 words / batch
#define PRIOR_VOX 4096              // 16^3
#define OCC_K 26
#define OCC_BASE ((size_t)NB * PRIOR_VOX)   // 33,554,432

// Scratch (static __device__ per harness rules): per-batch occupancy bitmap.
__device__ unsigned int g_bitmap[BATCH * BITMAP_WORDS];  // 128 KB

// 26 neighbor offsets; first 6 are the face offsets (order matches reference).
__constant__ int8_t c_noff[26][3] = {
    {-1,0,0},{1,0,0},{0,-1,0},{0,1,0},{0,0,-1},{0,0,1},
    {-1,-1,0},{-1,1,0},{1,-1,0},{1,1,0},
    {-1,0,-1},{-1,0,1},{1,0,-1},{1,0,1},
    {0,-1,-1},{0,-1,1},{0,1,-1},{0,1,1},
    {-1,-1,-1},{-1,-1,1},{-1,1,-1},{-1,1,1},
    {1,-1,-1},{1,-1,1},{1,1,-1},{1,1,1}};

// Fused zero + build ONLY (no probe here — probing on 4 SMs is LSU-bound).
// One CTA per batch, 1024 threads: 8 stores + 2 atomics per thread.
__global__ __launch_bounds__(1024)
void build_bitmap_kernel(const int* __restrict__ coords) {
    const int b = blockIdx.x;
    const int t = threadIdx.x;
    unsigned int* bm = g_bitmap + b * BITMAP_WORDS;

    #pragma unroll
    for (int i = 0; i < BITMAP_WORDS / 1024; i++)
        bm[t + i * 1024] = 0u;
    __syncthreads();

    const int* c = coords + b * NPTS * 3;
    #pragma unroll
    for (int i = 0; i < NPTS / 1024; i++) {
        int n = t + i * 1024;
        int x = c[n * 3 + 0];
        int y = c[n * 3 + 1];
        int z = c[n * 3 + 2];
        int idx = (x << 12) | (y << 6) | z;    // x*4096 + y*64 + z
        atomicOr(&bm[idx >> 5], 1u << (idx & 31));
    }
}

// One CTA per (b,n), 256 threads. Warp 0 lanes 0..25 each probe one neighbor
// (1 bitmap load), write occ, and ballot the face mask. Then all 256 threads
// stream the 4096-float prior tile: 4 fully contiguous warp-wide float4
// stores per thread. Probe cost is spread over 8192 CTAs -> negligible.
__global__ __launch_bounds__(256, 8)
void prior_occ_kernel(const int* __restrict__ coords, float* __restrict__ out) {
    const int bn = blockIdx.x;
    const int b  = bn >> 11;
    const int t  = threadIdx.x;

    __shared__ unsigned s_mask;

    if (t < 32) {
        const int x = coords[bn * 3 + 0];
        const int y = coords[bn * 3 + 1];
        const int z = coords[bn * 3 + 2];
        bool present = false;
        if (t < OCC_K) {
            int nx = x + c_noff[t][0];
            int ny = y + c_noff[t][1];
            int nz = z + c_noff[t][2];
            if ((unsigned)nx < GRID_DIM && (unsigned)ny < GRID_DIM &&
                (unsigned)nz < GRID_DIM) {
                int idx = (nx << 12) | (ny << 6) | nz;
                present = (g_bitmap[b * BITMAP_WORDS + (idx >> 5)] >> (idx & 31)) & 1u;
            }
            out[OCC_BASE + (size_t)bn * OCC_K + t] = present ? 1.0f : 0.0f;
        }
        unsigned bal = __ballot_sync(0xffffffffu, present);
        if (t == 0) s_mask = bal;
    }
    __syncthreads();

    const unsigned m = s_mask;
    const float r15 = 1.0f / 15.0f;
    float* out_p = out + (size_t)bn * PRIOR_VOX;

    // v = t*4 + q*1024; i = (t>>6) + 4q, j = (t>>2)&15, k0 = (t&3)*4.
    // y- and z-face mins are invariant across the 4 q iterations.
    const float gy = (float)((t >> 2) & 15) * r15;
    const int   k0 = (t & 3) << 2;
    const int   i0 = t >> 6;

    float ybase = 1.0f;
    if (!(m & 4u))  ybase = fminf(ybase, gy);
    if (!(m & 8u))  ybase = fminf(ybase, 1.0f - gy);

    float yz[4];
    #pragma unroll
    for (int kk = 0; kk < 4; kk++) {
        float gz = (float)(k0 + kk) * r15;
        float v = ybase;
        if (!(m & 16u)) v = fminf(v, gz);
        if (!(m & 32u)) v = fminf(v, 1.0f - gz);
        yz[kk] = v;
    }

    #pragma unroll
    for (int q = 0; q < 4; q++) {
        float gx = (float)(i0 + 4 * q) * r15;   // exact: matches linspace rounding
        float xv = 1.0f;
        if (!(m & 1u)) xv = fminf(xv, gx);
        if (!(m & 2u)) xv = fminf(xv, 1.0f - gx);
        float4 r;
        r.x = fminf(yz[0], xv);
        r.y = fminf(yz[1], xv);
        r.z = fminf(yz[2], xv);
        r.w = fminf(yz[3], xv);
        *reinterpret_cast<float4*>(out_p + (t << 2) + (q << 10)) = r;
    }
}

extern "C" void kernel_launch(void* const* d_in, const int* in_sizes, int n_in,
                              void* d_out, int out_size) {
    const int* coords = (const int*)d_in[0];
    float* out = (float*)d_out;

    build_bitmap_kernel<<<BATCH, 1024>>>(coords);
    prior_occ_kernel<<<NB, 256>>>(coords, out);
}